// round 2
// baseline (speedup 1.0000x reference)
#include <cuda_runtime.h>

// Problem constants
#define BB 16
#define NN 4096
#define SS 1024
#define KK 32
#define PTOT (BB*SS*KK)      // 524288 positions
#define C0 67
#define C1 64
#define C2 64
#define C3 128

// ---------------- device scratch (no allocation allowed) ----------------
__device__ float g_newxyz[BB*SS*3];
__device__ int   g_idx[BB*SS*KK];
__device__ float g_bufA[(size_t)PTOT*128];   // 256MB
__device__ float g_bufB[(size_t)PTOT*128];   // 256MB
__device__ float g_mu[128];
__device__ float g_var[128];

// =======================================================================
// 1) Farthest point sampling: one block per batch, bit-exact distance math
//    (matches JAX ((dx^2+dy^2)+dz^2) with no FMA contraction), first-index
//    argmax tie-break to match jnp.argmax.
// =======================================================================
__device__ __forceinline__ float sqdist_exact(float dx, float dy, float dz) {
    return __fadd_rn(__fadd_rn(__fmul_rn(dx, dx), __fmul_rn(dy, dy)), __fmul_rn(dz, dz));
}

__global__ __launch_bounds__(1024) void fps_kernel(const float* __restrict__ xyz) {
    int b = blockIdx.x, t = threadIdx.x;
    const float4* xb = (const float4*)(xyz + (size_t)b * 3 * NN);
    float4 X = xb[t];
    float4 Y = xb[NN/4 + t];
    float4 Z = xb[2*(NN/4) + t];
    float d0 = 1e10f, d1 = 1e10f, d2 = 1e10f, d3 = 1e10f;

    __shared__ float sv[32];
    __shared__ int   si[32];
    __shared__ float scx, scy, scz;
    __shared__ int   sfar;

    if (t == 0) { scx = X.x; scy = Y.x; scz = Z.x; }   // far = 0 initially
    __syncthreads();

    for (int s = 0; s < SS; s++) {
        float cx = scx, cy = scy, cz = scz;
        if (t == 0) {
            g_newxyz[(b*SS + s)*3 + 0] = cx;
            g_newxyz[(b*SS + s)*3 + 1] = cy;
            g_newxyz[(b*SS + s)*3 + 2] = cz;
        }
        d0 = fminf(d0, sqdist_exact(X.x - cx, Y.x - cy, Z.x - cz));
        d1 = fminf(d1, sqdist_exact(X.y - cx, Y.y - cy, Z.y - cz));
        d2 = fminf(d2, sqdist_exact(X.z - cx, Y.z - cy, Z.z - cz));
        d3 = fminf(d3, sqdist_exact(X.w - cx, Y.w - cy, Z.w - cz));

        // local argmax, ascending index => first-max semantics
        float bv = d0; int bi = 4*t;
        if (d1 > bv) { bv = d1; bi = 4*t + 1; }
        if (d2 > bv) { bv = d2; bi = 4*t + 2; }
        if (d3 > bv) { bv = d3; bi = 4*t + 3; }
        #pragma unroll
        for (int o = 16; o; o >>= 1) {
            float ov = __shfl_down_sync(0xffffffffu, bv, o);
            int   oi = __shfl_down_sync(0xffffffffu, bi, o);
            if (ov > bv || (ov == bv && oi < bi)) { bv = ov; bi = oi; }
        }
        if ((t & 31) == 0) { sv[t >> 5] = bv; si[t >> 5] = bi; }
        __syncthreads();
        if (t < 32) {
            bv = sv[t]; bi = si[t];
            #pragma unroll
            for (int o = 16; o; o >>= 1) {
                float ov = __shfl_down_sync(0xffffffffu, bv, o);
                int   oi = __shfl_down_sync(0xffffffffu, bi, o);
                if (ov > bv || (ov == bv && oi < bi)) { bv = ov; bi = oi; }
            }
            if (t == 0) sfar = bi;
        }
        __syncthreads();
        int far = sfar;
        if ((far >> 2) == t) {
            int r = far & 3;
            scx = (r == 0) ? X.x : (r == 1) ? X.y : (r == 2) ? X.z : X.w;
            scy = (r == 0) ? Y.x : (r == 1) ? Y.y : (r == 2) ? Y.z : Y.w;
            scz = (r == 0) ? Z.x : (r == 1) ? Z.y : (r == 2) ? Z.z : Z.w;
        }
        __syncthreads();
    }
}

// =======================================================================
// 2) Ball query: one warp per centroid, in-index-order first-32 selection
//    (matches sort-then-truncate in reference). 8 warps/block, xyz batch
//    staged in dynamic smem (48KB).
// =======================================================================
__global__ __launch_bounds__(256) void ball_kernel(const float* __restrict__ xyz) {
    extern __shared__ float sm[];                       // 12288 floats
    int b = (blockIdx.x * 8) >> 10;
    for (int i = threadIdx.x; i < 3*NN; i += 256)
        sm[i] = xyz[(size_t)b * 3 * NN + i];
    __syncthreads();
    const float* sx = sm;
    const float* sy = sm + NN;
    const float* sz = sm + 2*NN;

    int w = threadIdx.x >> 5, lane = threadIdx.x & 31;
    int bs = blockIdx.x * 8 + w;
    float cx = g_newxyz[bs*3], cy = g_newxyz[bs*3 + 1], cz = g_newxyz[bs*3 + 2];
    float snew = cx*cx + cy*cy + cz*cz;

    int cnt = 0, first = -1;
    for (int n0 = 0; n0 < NN && cnt < KK; n0 += 32) {
        int n = n0 + lane;
        float px = sx[n], py = sy[n], pz = sz[n];
        float sp = px*px + py*py + pz*pz;
        float d = snew + sp - 2.0f*(cx*px + cy*py + cz*pz);
        bool in = (d <= 0.04f);                        // radius^2 in f32
        unsigned m = __ballot_sync(0xffffffffu, in);
        if (first < 0 && m) first = n0 + __ffs(m) - 1;
        int rank = __popc(m & ((1u << lane) - 1u));
        if (in && cnt + rank < KK) g_idx[bs*KK + cnt + rank] = n;
        cnt += __popc(m);
    }
    if (lane >= cnt) g_idx[bs*KK + lane] = first;       // fill with first valid
}

// =======================================================================
// 3) Grouping: build feat [pos][67] = [xyz_gathered - center | points_gathered]
// =======================================================================
__global__ __launch_bounds__(256) void group_kernel(const float* __restrict__ xyz,
                                                    const float* __restrict__ pts) {
    int bs = blockIdx.x;
    int b = bs >> 10;
    __shared__ int sidx[KK];
    __shared__ float nx, ny, nz;
    if (threadIdx.x < KK) sidx[threadIdx.x] = g_idx[bs*KK + threadIdx.x];
    if (threadIdx.x == 0) {
        nx = g_newxyz[bs*3]; ny = g_newxyz[bs*3 + 1]; nz = g_newxyz[bs*3 + 2];
    }
    __syncthreads();
    for (int e = threadIdx.x; e < KK*C0; e += 256) {
        int k = e / C0, c = e - k*C0;
        int n = sidx[k];
        float v;
        if (c < 3) {
            float cen = (c == 0) ? nx : (c == 1) ? ny : nz;
            v = xyz[(size_t)b*3*NN + c*NN + n] - cen;
        } else {
            v = pts[((size_t)b*64 + (c - 3))*NN + n];
        }
        g_bufA[((size_t)bs*KK + k)*C0 + c] = v;
    }
}

// =======================================================================
// 4) 1x1 conv as GEMM: block = Cout*PP threads, each thread one output.
// =======================================================================
__global__ __launch_bounds__(256) void conv_kernel(const float* __restrict__ in,
                                                   float* __restrict__ out,
                                                   const float* __restrict__ W,
                                                   const float* __restrict__ bias,
                                                   int Cin, int Cout, int PP) {
    __shared__ float in_s[4*C0];                        // max PP*Cin = 268
    int pos0 = blockIdx.x * PP;
    int tot = PP * Cin;
    for (int i = threadIdx.x; i < tot; i += blockDim.x)
        in_s[i] = in[(size_t)pos0 * Cin + i];
    __syncthreads();
    int oc = threadIdx.x / PP;
    int p  = threadIdx.x - oc * PP;
    const float* wr = W + oc * Cin;
    const float* ir = in_s + p * Cin;
    float acc = 0.0f;
    for (int c = 0; c < Cin; c++) acc = fmaf(ir[c], wr[c], acc);
    out[(size_t)(pos0 + p) * Cout + oc] = acc + bias[oc];
}

// =======================================================================
// 5) Per-channel batch stats: one block per channel, deterministic tree.
// =======================================================================
__global__ __launch_bounds__(1024) void stats_kernel(const float* __restrict__ x, int C) {
    int c = blockIdx.x;
    float s = 0.0f, s2 = 0.0f;
    for (int p = threadIdx.x; p < PTOT; p += 1024) {
        float v = x[(size_t)p * C + c];
        s += v;
        s2 = fmaf(v, v, s2);
    }
    __shared__ float sh[64];
    #pragma unroll
    for (int o = 16; o; o >>= 1) {
        s  += __shfl_down_sync(0xffffffffu, s, o);
        s2 += __shfl_down_sync(0xffffffffu, s2, o);
    }
    int w = threadIdx.x >> 5, l = threadIdx.x & 31;
    if (l == 0) { sh[w] = s; sh[32 + w] = s2; }
    __syncthreads();
    if (threadIdx.x < 32) {
        s = sh[threadIdx.x]; s2 = sh[32 + threadIdx.x];
        #pragma unroll
        for (int o = 16; o; o >>= 1) {
            s  += __shfl_down_sync(0xffffffffu, s, o);
            s2 += __shfl_down_sync(0xffffffffu, s2, o);
        }
        if (threadIdx.x == 0) {
            float m = s / (float)PTOT;
            g_mu[c] = m;
            g_var[c] = s2 / (float)PTOT - m * m;
        }
    }
}

// =======================================================================
// 6) BN (batch stats) + ReLU, in place
// =======================================================================
__global__ __launch_bounds__(256) void bnrelu_kernel(float* __restrict__ x, int C, int total,
                                                     const float* __restrict__ g,
                                                     const float* __restrict__ bt) {
    int i = blockIdx.x * 256 + threadIdx.x;
    if (i >= total) return;
    int c = i % C;
    float v = (x[i] - g_mu[c]) * rsqrtf(g_var[c] + 1e-5f) * g[c] + bt[c];
    x[i] = v > 0.0f ? v : 0.0f;
}

// =======================================================================
// 7) Max-pool over K and transpose to [B, 128, S] into output tail
// =======================================================================
__global__ __launch_bounds__(128) void maxpool_kernel(const float* __restrict__ x,
                                                      float* __restrict__ out) {
    int bs = blockIdx.x;
    int c = threadIdx.x;
    size_t base = (size_t)bs * KK * C3 + c;
    float m = -1e30f;
    #pragma unroll
    for (int k = 0; k < KK; k++) m = fmaxf(m, x[base + (size_t)k * C3]);
    int b = bs >> 10, s = bs & 1023;
    out[(size_t)BB*3*SS + ((size_t)b * C3 + c) * SS + s] = m;
}

// 8) new_xyz transpose to [B, 3, S] at output head
__global__ __launch_bounds__(256) void outxyz_kernel(float* __restrict__ out) {
    int i = blockIdx.x * 256 + threadIdx.x;
    if (i >= BB*3*SS) return;
    int s = i & 1023;
    int bd = i >> 10;
    int b = bd / 3, d = bd - b * 3;
    out[i] = g_newxyz[((size_t)b * SS + s) * 3 + d];
}

// =======================================================================
extern "C" void kernel_launch(void* const* d_in, const int* in_sizes, int n_in,
                              void* d_out, int out_size) {
    const float* xyz = (const float*)d_in[0];
    const float* pts = (const float*)d_in[1];
    const float* w0  = (const float*)d_in[2];
    const float* b0  = (const float*)d_in[3];
    const float* g0  = (const float*)d_in[4];
    const float* bt0 = (const float*)d_in[5];
    const float* w1  = (const float*)d_in[6];
    const float* b1  = (const float*)d_in[7];
    const float* g1  = (const float*)d_in[8];
    const float* bt1 = (const float*)d_in[9];
    const float* w2  = (const float*)d_in[10];
    const float* b2  = (const float*)d_in[11];
    const float* g2  = (const float*)d_in[12];
    const float* bt2 = (const float*)d_in[13];
    float* out = (float*)d_out;

    float *pA = nullptr, *pB = nullptr;
    cudaGetSymbolAddress((void**)&pA, g_bufA);
    cudaGetSymbolAddress((void**)&pB, g_bufB);

    fps_kernel<<<BB, 1024>>>(xyz);
    ball_kernel<<<(BB*SS)/8, 256, 3*NN*sizeof(float)>>>(xyz);
    group_kernel<<<BB*SS, 256>>>(xyz, pts);

    // Layer 1: 67 -> 64 (bufA -> bufB)
    conv_kernel<<<PTOT/4, 256>>>(pA, pB, w0, b0, C0, C1, 4);
    stats_kernel<<<C1, 1024>>>(pB, C1);
    bnrelu_kernel<<<(PTOT*C1)/256, 256>>>(pB, C1, PTOT*C1, g0, bt0);

    // Layer 2: 64 -> 64 (bufB -> bufA)
    conv_kernel<<<PTOT/4, 256>>>(pB, pA, w1, b1, C1, C2, 4);
    stats_kernel<<<C2, 1024>>>(pA, C2);
    bnrelu_kernel<<<(PTOT*C2)/256, 256>>>(pA, C2, PTOT*C2, g1, bt1);

    // Layer 3: 64 -> 128 (bufA -> bufB)
    conv_kernel<<<PTOT/2, 256>>>(pA, pB, w2, b2, C2, C3, 2);
    stats_kernel<<<C3, 1024>>>(pB, C3);
    bnrelu_kernel<<<(PTOT*C3)/256, 256>>>(pB, C3, PTOT*C3, g2, bt2);

    maxpool_kernel<<<BB*SS, 128>>>(pB, out);
    outxyz_kernel<<<(BB*3*SS + 255)/256, 256>>>(out);
}

// round 3
// speedup vs baseline: 7.9057x; 7.9057x over previous
#include <cuda_runtime.h>

// Problem constants
#define BB 16
#define NN 4096
#define SS 1024
#define KK 32
#define PTOT (BB*SS*KK)      // 524288 positions
#define C0 67
#define C1 64
#define C3 128
#define NBLK (PTOT/128)      // 4096 GEMM blocks

typedef unsigned long long u64;

// ---------------- device scratch (no allocation allowed) ----------------
__device__ float g_newxyz[BB*SS*3];
__device__ int   g_idx[BB*SS*KK];
__device__ float g_bufA[(size_t)PTOT*128];   // 256MB
__device__ float g_bufB[(size_t)PTOT*128];   // 256MB
__device__ float g_psum[128*NBLK];
__device__ float g_psq[128*NBLK];
__device__ float g_scale[128];
__device__ float g_shift[128];
__device__ float g_wt[128*128];

// ---------------- f32x2 helpers ----------------
__device__ __forceinline__ u64 pk2(float x, float y) {
    u64 r; asm("mov.b64 %0, {%1,%2};" : "=l"(r) : "f"(x), "f"(y)); return r;
}
__device__ __forceinline__ void upk2(u64 v, float& x, float& y) {
    asm("mov.b64 {%0,%1}, %2;" : "=f"(x), "=f"(y) : "l"(v));
}
__device__ __forceinline__ void ffma2(u64& d, u64 a, u64 b) {
    asm("fma.rn.f32x2 %0, %1, %2, %0;" : "+l"(d) : "l"(a), "l"(b));
}

// =======================================================================
// 1) Farthest point sampling (bit-exact distance math, first-max argmax)
// =======================================================================
__device__ __forceinline__ float sqdist_exact(float dx, float dy, float dz) {
    return __fadd_rn(__fadd_rn(__fmul_rn(dx, dx), __fmul_rn(dy, dy)), __fmul_rn(dz, dz));
}

__global__ __launch_bounds__(1024) void fps_kernel(const float* __restrict__ xyz) {
    int b = blockIdx.x, t = threadIdx.x;
    const float4* xb = (const float4*)(xyz + (size_t)b * 3 * NN);
    float4 X = xb[t];
    float4 Y = xb[NN/4 + t];
    float4 Z = xb[2*(NN/4) + t];
    float d0 = 1e10f, d1 = 1e10f, d2 = 1e10f, d3 = 1e10f;

    __shared__ float sv[32];
    __shared__ int   si[32];
    __shared__ float scx, scy, scz;
    __shared__ int   sfar;

    if (t == 0) { scx = X.x; scy = Y.x; scz = Z.x; }
    __syncthreads();

    for (int s = 0; s < SS; s++) {
        float cx = scx, cy = scy, cz = scz;
        if (t == 0) {
            g_newxyz[(b*SS + s)*3 + 0] = cx;
            g_newxyz[(b*SS + s)*3 + 1] = cy;
            g_newxyz[(b*SS + s)*3 + 2] = cz;
        }
        d0 = fminf(d0, sqdist_exact(X.x - cx, Y.x - cy, Z.x - cz));
        d1 = fminf(d1, sqdist_exact(X.y - cx, Y.y - cy, Z.y - cz));
        d2 = fminf(d2, sqdist_exact(X.z - cx, Y.z - cy, Z.z - cz));
        d3 = fminf(d3, sqdist_exact(X.w - cx, Y.w - cy, Z.w - cz));

        float bv = d0; int bi = 4*t;
        if (d1 > bv) { bv = d1; bi = 4*t + 1; }
        if (d2 > bv) { bv = d2; bi = 4*t + 2; }
        if (d3 > bv) { bv = d3; bi = 4*t + 3; }
        #pragma unroll
        for (int o = 16; o; o >>= 1) {
            float ov = __shfl_down_sync(0xffffffffu, bv, o);
            int   oi = __shfl_down_sync(0xffffffffu, bi, o);
            if (ov > bv || (ov == bv && oi < bi)) { bv = ov; bi = oi; }
        }
        if ((t & 31) == 0) { sv[t >> 5] = bv; si[t >> 5] = bi; }
        __syncthreads();
        if (t < 32) {
            bv = sv[t]; bi = si[t];
            #pragma unroll
            for (int o = 16; o; o >>= 1) {
                float ov = __shfl_down_sync(0xffffffffu, bv, o);
                int   oi = __shfl_down_sync(0xffffffffu, bi, o);
                if (ov > bv || (ov == bv && oi < bi)) { bv = ov; bi = oi; }
            }
            if (t == 0) sfar = bi;
        }
        __syncthreads();
        int far = sfar;
        if ((far >> 2) == t) {
            int r = far & 3;
            scx = (r == 0) ? X.x : (r == 1) ? X.y : (r == 2) ? X.z : X.w;
            scy = (r == 0) ? Y.x : (r == 1) ? Y.y : (r == 2) ? Y.z : Y.w;
            scz = (r == 0) ? Z.x : (r == 1) ? Z.y : (r == 2) ? Z.z : Z.w;
        }
        __syncthreads();
    }
}

// =======================================================================
// 2) Ball query (in-index-order first-32 selection)
// =======================================================================
__global__ __launch_bounds__(256) void ball_kernel(const float* __restrict__ xyz) {
    extern __shared__ float smb[];
    int b = (blockIdx.x * 8) >> 10;
    for (int i = threadIdx.x; i < 3*NN; i += 256)
        smb[i] = xyz[(size_t)b * 3 * NN + i];
    __syncthreads();
    const float* sx = smb;
    const float* sy = smb + NN;
    const float* sz = smb + 2*NN;

    int w = threadIdx.x >> 5, lane = threadIdx.x & 31;
    int bs = blockIdx.x * 8 + w;
    float cx = g_newxyz[bs*3], cy = g_newxyz[bs*3 + 1], cz = g_newxyz[bs*3 + 2];
    float snew = cx*cx + cy*cy + cz*cz;

    int cnt = 0, first = -1;
    for (int n0 = 0; n0 < NN && cnt < KK; n0 += 32) {
        int n = n0 + lane;
        float px = sx[n], py = sy[n], pz = sz[n];
        float sp = px*px + py*py + pz*pz;
        float d = snew + sp - 2.0f*(cx*px + cy*py + cz*pz);
        bool in = (d <= 0.04f);
        unsigned m = __ballot_sync(0xffffffffu, in);
        if (first < 0 && m) first = n0 + __ffs(m) - 1;
        int rank = __popc(m & ((1u << lane) - 1u));
        if (in && cnt + rank < KK) g_idx[bs*KK + cnt + rank] = n;
        cnt += __popc(m);
    }
    if (lane >= cnt) g_idx[bs*KK + lane] = first;
}

// =======================================================================
// 3) Grouping -> channel-major feat0 [C0][PTOT]
// =======================================================================
__global__ __launch_bounds__(256) void group_kernel(const float* __restrict__ xyz,
                                                    const float* __restrict__ pts,
                                                    float* __restrict__ feat) {
    int bs = blockIdx.x;
    int b = bs >> 10;
    int t = threadIdx.x;
    __shared__ int sidx[KK];
    __shared__ float ctr[3];
    if (t < KK) sidx[t] = g_idx[bs*KK + t];
    if (t < 3)  ctr[t] = g_newxyz[bs*3 + t];
    __syncthreads();
    int lane = t & 31, w = t >> 5;
    int n = sidx[lane];
    for (int c = w; c < C0; c += 8) {
        float v;
        if (c < 3) v = xyz[(size_t)b*3*NN + c*NN + n] - ctr[c];
        else       v = pts[((size_t)b*64 + (c - 3))*NN + n];
        feat[(size_t)c*PTOT + bs*KK + lane] = v;
    }
}

// =======================================================================
// 4) Weight transpose: wt[k][m] = W[m][k]
// =======================================================================
__global__ void wtrans_kernel(const float* __restrict__ W, float* __restrict__ wt,
                              int M, int K) {
    int i = blockIdx.x * 256 + threadIdx.x;
    if (i < M*K) { int k = i / M, m = i - k*M; wt[i] = W[m*K + k]; }
}

// =======================================================================
// 5) GEMM: out[M][PTOT] = Wt^T x in[K][PTOT] (+bias), optional fused
//    BN+ReLU on the input load, per-block BN stats partials in epilogue.
//    Block tile M x 128, thread tile (M/16) x 8, FFMA2 inner product.
// =======================================================================
extern __shared__ float smg[];

template<int M, int K, bool BN>
__global__ __launch_bounds__(256) void gemm_kernel(const float* __restrict__ in,
                                                   float* __restrict__ out,
                                                   const float* __restrict__ wt,
                                                   const float* __restrict__ bias,
                                                   float* __restrict__ psum,
                                                   float* __restrict__ psq) {
    constexpr int TM = M / 16;
    float* sW = smg;            // K*M floats
    float* sA = smg + K*M;      // K*128 floats
    const int t = threadIdx.x;
    const int tn = t & 15, tm = t >> 4;
    const int n0 = blockIdx.x * 128;

    for (int i = t; i < K*M; i += 256) sW[i] = wt[i];
    for (int i = t; i < K*32; i += 256) {
        int k = i >> 5, c = (i & 31) << 2;
        float4 v = *(const float4*)(in + (size_t)k*PTOT + n0 + c);
        if (BN) {
            float sc = g_scale[k], sh = g_shift[k];
            v.x = fmaxf(fmaf(v.x, sc, sh), 0.0f);
            v.y = fmaxf(fmaf(v.y, sc, sh), 0.0f);
            v.z = fmaxf(fmaf(v.z, sc, sh), 0.0f);
            v.w = fmaxf(fmaf(v.w, sc, sh), 0.0f);
        }
        *(float4*)(sA + k*128 + c) = v;
    }
    __syncthreads();

    u64 acc[TM][4];
    #pragma unroll
    for (int j = 0; j < TM; j++)
        #pragma unroll
        for (int q = 0; q < 4; q++) acc[j][q] = 0ull;

    #pragma unroll 4
    for (int k = 0; k < K; k++) {
        ulonglong2 av0 = *(const ulonglong2*)(sA + k*128 + tn*8);
        ulonglong2 av1 = *(const ulonglong2*)(sA + k*128 + tn*8 + 4);
        #pragma unroll
        for (int j = 0; j < TM; j += 4) {
            float4 wv = *(const float4*)(sW + k*M + tm*TM + j);
            u64 w0 = pk2(wv.x, wv.x);
            u64 w1 = pk2(wv.y, wv.y);
            u64 w2 = pk2(wv.z, wv.z);
            u64 w3 = pk2(wv.w, wv.w);
            ffma2(acc[j+0][0], av0.x, w0); ffma2(acc[j+0][1], av0.y, w0);
            ffma2(acc[j+0][2], av1.x, w0); ffma2(acc[j+0][3], av1.y, w0);
            ffma2(acc[j+1][0], av0.x, w1); ffma2(acc[j+1][1], av0.y, w1);
            ffma2(acc[j+1][2], av1.x, w1); ffma2(acc[j+1][3], av1.y, w1);
            ffma2(acc[j+2][0], av0.x, w2); ffma2(acc[j+2][1], av0.y, w2);
            ffma2(acc[j+2][2], av1.x, w2); ffma2(acc[j+2][3], av1.y, w2);
            ffma2(acc[j+3][0], av0.x, w3); ffma2(acc[j+3][1], av0.y, w3);
            ffma2(acc[j+3][2], av1.x, w3); ffma2(acc[j+3][3], av1.y, w3);
        }
    }

    // epilogue: bias add, store, per-thread partial stats
    float ps[TM], pq[TM];
    #pragma unroll
    for (int j = 0; j < TM; j++) {
        int m = tm*TM + j;
        float b = bias[m];
        float vals[8];
        #pragma unroll
        for (int q = 0; q < 4; q++) {
            float x, y; upk2(acc[j][q], x, y);
            vals[2*q] = x + b; vals[2*q + 1] = y + b;
        }
        *(float4*)(out + (size_t)m*PTOT + n0 + tn*8)     = make_float4(vals[0], vals[1], vals[2], vals[3]);
        *(float4*)(out + (size_t)m*PTOT + n0 + tn*8 + 4) = make_float4(vals[4], vals[5], vals[6], vals[7]);
        float s = 0.0f, q2 = 0.0f;
        #pragma unroll
        for (int p = 0; p < 8; p++) { s += vals[p]; q2 = fmaf(vals[p], vals[p], q2); }
        ps[j] = s; pq[j] = q2;
    }
    __syncthreads();               // sA no longer needed; reuse for reduction
    float* red = sA;               // [M][16] sums then [M][16] sq
    #pragma unroll
    for (int j = 0; j < TM; j++) {
        int m = tm*TM + j;
        red[m*16 + tn] = ps[j];
        red[M*16 + m*16 + tn] = pq[j];
    }
    __syncthreads();
    if (t < M) {
        float s = 0.0f, q2 = 0.0f;
        #pragma unroll
        for (int i = 0; i < 16; i++) { s += red[t*16 + i]; q2 += red[M*16 + t*16 + i]; }
        psum[(size_t)t*NBLK + blockIdx.x] = s;
        psq [(size_t)t*NBLK + blockIdx.x] = q2;
    }
}

// =======================================================================
// 6) Reduce partials -> BN scale/shift (deterministic tree)
// =======================================================================
__global__ __launch_bounds__(256) void reduce_stats_kernel(const float* __restrict__ psum,
                                                           const float* __restrict__ psq,
                                                           const float* __restrict__ g,
                                                           const float* __restrict__ bt) {
    int c = blockIdx.x, t = threadIdx.x;
    float s = 0.0f, q = 0.0f;
    for (int i = t; i < NBLK; i += 256) {
        s += psum[(size_t)c*NBLK + i];
        q += psq [(size_t)c*NBLK + i];
    }
    __shared__ float ss[256], sq[256];
    ss[t] = s; sq[t] = q;
    __syncthreads();
    for (int o = 128; o; o >>= 1) {
        if (t < o) { ss[t] += ss[t + o]; sq[t] += sq[t + o]; }
        __syncthreads();
    }
    if (t == 0) {
        float mu  = ss[0] / (float)PTOT;
        float var = sq[0] / (float)PTOT - mu * mu;
        float sc  = rsqrtf(var + 1e-5f) * g[c];
        g_scale[c] = sc;
        g_shift[c] = bt[c] - mu * sc;
    }
}

// =======================================================================
// 7) Fused BN+ReLU+max-pool over K, write transposed [B][128][S]
// =======================================================================
__global__ __launch_bounds__(256) void maxpool_kernel(const float* __restrict__ x,
                                                      float* __restrict__ out) {
    int c = blockIdx.x >> 4, b = blockIdx.x & 15;
    float sc = g_scale[c], sh = g_shift[c];
    for (int s = threadIdx.x; s < SS; s += 256) {
        const float4* p = (const float4*)(x + (size_t)c*PTOT + (size_t)(b*SS + s)*KK);
        float mx = -3.4e38f, mn = 3.4e38f;
        #pragma unroll
        for (int q = 0; q < 8; q++) {
            float4 v = p[q];
            mx = fmaxf(mx, fmaxf(fmaxf(v.x, v.y), fmaxf(v.z, v.w)));
            mn = fminf(mn, fminf(fminf(v.x, v.y), fminf(v.z, v.w)));
        }
        float r = fmaf((sc >= 0.0f ? mx : mn), sc, sh);
        out[(size_t)BB*3*SS + ((size_t)(b*C3 + c))*SS + s] = fmaxf(r, 0.0f);
    }
}

// 8) new_xyz transpose to [B, 3, S] at output head
__global__ __launch_bounds__(256) void outxyz_kernel(float* __restrict__ out) {
    int i = blockIdx.x * 256 + threadIdx.x;
    if (i >= BB*3*SS) return;
    int s = i & 1023;
    int bd = i >> 10;
    int b = bd / 3, d = bd - b * 3;
    out[i] = g_newxyz[((size_t)b * SS + s) * 3 + d];
}

// =======================================================================
extern "C" void kernel_launch(void* const* d_in, const int* in_sizes, int n_in,
                              void* d_out, int out_size) {
    const float* xyz = (const float*)d_in[0];
    const float* pts = (const float*)d_in[1];
    const float* w0  = (const float*)d_in[2];
    const float* b0  = (const float*)d_in[3];
    const float* g0  = (const float*)d_in[4];
    const float* bt0 = (const float*)d_in[5];
    const float* w1  = (const float*)d_in[6];
    const float* b1  = (const float*)d_in[7];
    const float* g1  = (const float*)d_in[8];
    const float* bt1 = (const float*)d_in[9];
    const float* w2  = (const float*)d_in[10];
    const float* b2  = (const float*)d_in[11];
    const float* g2  = (const float*)d_in[12];
    const float* bt2 = (const float*)d_in[13];
    float* out = (float*)d_out;

    float *pA = nullptr, *pB = nullptr, *pwt = nullptr, *pps = nullptr, *ppq = nullptr;
    cudaGetSymbolAddress((void**)&pA, g_bufA);
    cudaGetSymbolAddress((void**)&pB, g_bufB);
    cudaGetSymbolAddress((void**)&pwt, g_wt);
    cudaGetSymbolAddress((void**)&pps, g_psum);
    cudaGetSymbolAddress((void**)&ppq, g_psq);

    const int smem1 = (C0*C1 + C0*128) * 4;   // 51456
    const int smem2 = (C1*C1 + C1*128) * 4;   // 49152
    const int smem3 = (C1*C3 + C1*128) * 4;   // 65536
    cudaFuncSetAttribute(gemm_kernel<64, 67, false>, cudaFuncAttributeMaxDynamicSharedMemorySize, smem1);
    cudaFuncSetAttribute(gemm_kernel<64, 64, true>,  cudaFuncAttributeMaxDynamicSharedMemorySize, smem2);
    cudaFuncSetAttribute(gemm_kernel<128, 64, true>, cudaFuncAttributeMaxDynamicSharedMemorySize, smem3);

    fps_kernel<<<BB, 1024>>>(xyz);
    ball_kernel<<<(BB*SS)/8, 256, 3*NN*sizeof(float)>>>(xyz);
    group_kernel<<<BB*SS, 256>>>(xyz, pts, pA);

    // Layer 1: 67 -> 64 (A -> B)
    wtrans_kernel<<<(C1*C0 + 255)/256, 256>>>(w0, pwt, C1, C0);
    gemm_kernel<64, 67, false><<<NBLK, 256, smem1>>>(pA, pB, pwt, b0, pps, ppq);
    reduce_stats_kernel<<<C1, 256>>>(pps, ppq, g0, bt0);

    // Layer 2: 64 -> 64 (B -> A), BN+ReLU fused on load
    wtrans_kernel<<<(C1*C1 + 255)/256, 256>>>(w1, pwt, C1, C1);
    gemm_kernel<64, 64, true><<<NBLK, 256, smem2>>>(pB, pA, pwt, b1, pps, ppq);
    reduce_stats_kernel<<<C1, 256>>>(pps, ppq, g1, bt1);

    // Layer 3: 64 -> 128 (A -> B), BN+ReLU fused on load
    wtrans_kernel<<<(C3*C1 + 255)/256, 256>>>(w2, pwt, C3, C1);
    gemm_kernel<128, 64, true><<<NBLK, 256, smem3>>>(pA, pB, pwt, b2, pps, ppq);
    reduce_stats_kernel<<<C3, 256>>>(pps, ppq, g2, bt2);

    // Fused BN+ReLU+maxpool + output transposes
    maxpool_kernel<<<C3*BB, 256>>>(pB, out);
    outxyz_kernel<<<(BB*3*SS + 255)/256, 256>>>(out);
}

// round 8
// speedup vs baseline: 8.4539x; 1.0693x over previous
#include <cuda_runtime.h>

// Problem constants
#define BB 16
#define NN 4096
#define SS 1024
#define KK 32
#define PTOT (BB*SS*KK)      // 524288 positions
#define C0 67
#define C1 64
#define C3 128

typedef unsigned long long u64;

// ---------------- device scratch (no allocation allowed) ----------------
__device__ float g_newxyz[BB*SS*3];
__device__ float g_ptsT[(size_t)BB*NN*64];   // 16MB  [b][n][c]
__device__ float g_bufA[(size_t)PTOT*128];   // 256MB
__device__ float g_bufB[(size_t)PTOT*128];   // 256MB
__device__ float g_psum[128*4096];
__device__ float g_psq[128*4096];
__device__ float g_scale[128];
__device__ float g_shift[128];
__device__ float g_wt0[C0*C1];
__device__ float g_wt1[C1*C1];
__device__ float g_wt2[C1*C3];
__device__ int   g_flag[BB];                 // fps done per batch
__device__ int   g_tdone;                    // transpose barrier

// ---------------- f32x2 helpers ----------------
__device__ __forceinline__ u64 pk2(float x, float y) {
    u64 r; asm("mov.b64 %0, {%1,%2};" : "=l"(r) : "f"(x), "f"(y)); return r;
}
__device__ __forceinline__ void upk2(u64 v, float& x, float& y) {
    asm("mov.b64 {%0,%1}, %2;" : "=f"(x), "=f"(y) : "l"(v));
}
__device__ __forceinline__ void ffma2(u64& d, u64 a, u64 b) {
    asm("fma.rn.f32x2 %0, %1, %2, %0;" : "+l"(d) : "l"(a), "l"(b));
}

__device__ __forceinline__ float sqdist_exact(float dx, float dy, float dz) {
    return __fadd_rn(__fadd_rn(__fmul_rn(dx, dx), __fmul_rn(dy, dy)), __fmul_rn(dz, dz));
}

// =======================================================================
// 0) reset flags (must run every replay)
// =======================================================================
__global__ void reset_kernel() {
    int t = threadIdx.x;
    if (t < BB) g_flag[t] = 0;
    if (t == BB) g_tdone = 0;
}

// =======================================================================
// 1) MEGA front-end kernel: 144 blocks x 1024 threads, all resident.
//    Blocks 0..15:  FPS (one per batch), sets g_flag[b] when done.
//    Blocks 16..143: pts transpose share -> barrier -> wait flag[b] ->
//                    ball query + grouping for their 128 centroids.
// =======================================================================
extern __shared__ float smd[];

__global__ __launch_bounds__(1024) void mega_kernel(const float* __restrict__ xyz,
                                                    const float* __restrict__ pts,
                                                    float* __restrict__ ptsT,
                                                    float* __restrict__ feat) {
    const int t = threadIdx.x;
    const int w = t >> 5, lane = t & 31;

    if (blockIdx.x < BB) {
        // ---------------- FPS ----------------
        int b = blockIdx.x;
        for (int i = t; i < 3*NN; i += 1024)
            smd[i] = xyz[(size_t)b*3*NN + i];
        __syncthreads();

        float4 X = ((const float4*)smd)[t];
        float4 Y = ((const float4*)(smd + NN))[t];
        float4 Z = ((const float4*)(smd + 2*NN))[t];
        float d0 = 1e10f, d1 = 1e10f, d2 = 1e10f, d3 = 1e10f;

        unsigned* sv = (unsigned*)(smd + 3*NN);   // 32 keys
        int*      si = (int*)(smd + 3*NN + 32);   // 32 idx
        int*      sfar = (int*)(smd + 3*NN + 64);

        int far = 0;
        for (int s = 0; s < SS; s++) {
            float cx = smd[far], cy = smd[NN + far], cz = smd[2*NN + far];
            if (t == 0) {
                g_newxyz[(b*SS + s)*3 + 0] = cx;
                g_newxyz[(b*SS + s)*3 + 1] = cy;
                g_newxyz[(b*SS + s)*3 + 2] = cz;
            }
            d0 = fminf(d0, sqdist_exact(X.x - cx, Y.x - cy, Z.x - cz));
            d1 = fminf(d1, sqdist_exact(X.y - cx, Y.y - cy, Z.y - cz));
            d2 = fminf(d2, sqdist_exact(X.z - cx, Y.z - cy, Z.z - cz));
            d3 = fminf(d3, sqdist_exact(X.w - cx, Y.w - cy, Z.w - cz));

            float bv = d0; int bi = 4*t;
            if (d1 > bv) { bv = d1; bi = 4*t + 1; }
            if (d2 > bv) { bv = d2; bi = 4*t + 2; }
            if (d3 > bv) { bv = d3; bi = 4*t + 3; }

            unsigned key = __float_as_uint(bv);           // nonneg -> order-preserving
            unsigned wm = __reduce_max_sync(0xffffffffu, key);
            unsigned mm = __ballot_sync(0xffffffffu, key == wm);
            int ln = __ffs(mm) - 1;                       // lowest lane = first max
            int wbi = __shfl_sync(0xffffffffu, bi, ln);
            if (lane == 0) { sv[w] = wm; si[w] = wbi; }
            __syncthreads();
            if (t < 32) {
                unsigned k2 = sv[t]; int i2 = si[t];
                unsigned wm2 = __reduce_max_sync(0xffffffffu, k2);
                unsigned m2 = __ballot_sync(0xffffffffu, k2 == wm2);
                int l2 = __ffs(m2) - 1;
                int f2 = __shfl_sync(0xffffffffu, i2, l2);
                if (t == 0) *sfar = f2;
            }
            __syncthreads();
            far = *sfar;
        }
        __threadfence();
        if (t == 0) atomicExch(&g_flag[b], 1);
        return;
    }

    // ---------------- workers ----------------
    int wb = blockIdx.x - BB;          // 0..127
    int b = wb >> 3, sub = wb & 7;

    // Phase A: pts transpose share (32 tiles of 32x32)
    {
        float* tile = smd;             // 32x33
        for (int tix = wb*32; tix < wb*32 + 32; tix++) {
            int tb = tix >> 8, rem = tix & 255;
            int ct = rem >> 7, nt = rem & 127;
            tile[lane*33 + w] = pts[((size_t)tb*64 + ct*32 + w)*NN + nt*32 + lane];
            __syncthreads();
            ptsT[((size_t)tb*NN + nt*32 + w)*64 + ct*32 + lane] = tile[w*33 + lane];
            __syncthreads();
        }
        __threadfence();
        if (t == 0) atomicAdd(&g_tdone, 1);
    }
    // wait all transposes (group gathers may cross our share's boundaries)
    if (t == 0) { while (atomicAdd(&g_tdone, 0) < 128) __nanosleep(128); }
    // wait fps for our batch
    if (t == 0) { while (atomicAdd(&g_flag[b], 0) == 0) __nanosleep(256); }
    __syncthreads();
    __threadfence();

    // load xyz[b] into smem
    for (int i = t; i < 3*NN; i += 1024)
        smd[i] = xyz[(size_t)b*3*NN + i];
    __syncthreads();

    int* sIdx = (int*)(smd + 3*NN);    // [32 warps][32]

    for (int r = 0; r < 4; r++) {
        int bs = b*1024 + sub*128 + w*4 + r;
        // ---- ball query (warp) ----
        float cx = g_newxyz[bs*3], cy = g_newxyz[bs*3 + 1], cz = g_newxyz[bs*3 + 2];
        float snew = cx*cx + cy*cy + cz*cz;
        int cnt = 0, first = -1;
        for (int n0 = 0; n0 < NN && cnt < KK; n0 += 32) {
            int n = n0 + lane;
            float px = smd[n], py = smd[NN + n], pz = smd[2*NN + n];
            float sp = px*px + py*py + pz*pz;
            float d = snew + sp - 2.0f*(cx*px + cy*py + cz*pz);
            bool in = (d <= 0.04f);
            unsigned m = __ballot_sync(0xffffffffu, in);
            if (first < 0 && m) first = n0 + __ffs(m) - 1;
            int rank = __popc(m & ((1u << lane) - 1u));
            if (in && cnt + rank < KK) sIdx[w*32 + cnt + rank] = n;
            cnt += __popc(m);
        }
        if (lane >= cnt) sIdx[w*32 + lane] = first;
        __syncwarp();

        // ---- grouping (warp, lane = sample) ----
        int n = sIdx[w*32 + lane];
        #pragma unroll
        for (int c = 0; c < 3; c++)
            feat[(size_t)c*PTOT + bs*KK + lane] = smd[c*NN + n] - g_newxyz[bs*3 + c];
        const float4* row = (const float4*)(ptsT + ((size_t)b*NN + n)*64);
        #pragma unroll
        for (int c4 = 0; c4 < 16; c4++) {
            float4 v = row[c4];
            feat[(size_t)(3 + 4*c4 + 0)*PTOT + bs*KK + lane] = v.x;
            feat[(size_t)(3 + 4*c4 + 1)*PTOT + bs*KK + lane] = v.y;
            feat[(size_t)(3 + 4*c4 + 2)*PTOT + bs*KK + lane] = v.z;
            feat[(size_t)(3 + 4*c4 + 3)*PTOT + bs*KK + lane] = v.w;
        }
        __syncwarp();
    }
}

// =======================================================================
// 2) All three weight transposes in one launch: wt[k][m] = W[m][k]
// =======================================================================
__global__ void wtrans_all_kernel(const float* __restrict__ w0,
                                  const float* __restrict__ w1,
                                  const float* __restrict__ w2) {
    int i = blockIdx.x * 256 + threadIdx.x;
    if (i < C0*C1) {
        int k = i / C1, m = i - k*C1;
        g_wt0[i] = w0[m*C0 + k];
    } else if (i < C0*C1 + C1*C1) {
        int j = i - C0*C1, k = j / C1, m = j - k*C1;
        g_wt1[j] = w1[m*C1 + k];
    } else if (i < C0*C1 + C1*C1 + C1*C3) {
        int j = i - C0*C1 - C1*C1, k = j / C3, m = j - k*C3;
        g_wt2[j] = w2[m*C1 + k];
    }
}

// =======================================================================
// 3) GEMM: out[M][PTOT] = Wt^T x in[K][PTOT] (+bias). Optional BN+ReLU
//    fused on input load; per-block BN-stat partials in epilogue.
//    Block tile M x (16*TN), thread tile TM x TN, FFMA2.
// =======================================================================
extern __shared__ float smg[];

template<int M, int K, int TN, bool BN>
__global__ __launch_bounds__(256) void gemm_kernel(const float* __restrict__ in,
                                                   float* __restrict__ out,
                                                   const float* __restrict__ wt,
                                                   const float* __restrict__ bias,
                                                   float* __restrict__ psum,
                                                   float* __restrict__ psq,
                                                   int nblk) {
    constexpr int TM = M / 16;
    constexpr int NT = 16 * TN;
    float* sW = smg;            // K*M
    float* sA = smg + K*M;      // K*NT
    const int t = threadIdx.x;
    const int tn = t & 15, tm = t >> 4;
    const int n0 = blockIdx.x * NT;

    for (int i = t; i < K*M; i += 256) sW[i] = wt[i];
    for (int i = t; i < K*(NT/4); i += 256) {
        int k = i / (NT/4), c = (i % (NT/4)) << 2;
        float4 v = *(const float4*)(in + (size_t)k*PTOT + n0 + c);
        if (BN) {
            float sc = g_scale[k], sh = g_shift[k];
            v.x = fmaxf(fmaf(v.x, sc, sh), 0.0f);
            v.y = fmaxf(fmaf(v.y, sc, sh), 0.0f);
            v.z = fmaxf(fmaf(v.z, sc, sh), 0.0f);
            v.w = fmaxf(fmaf(v.w, sc, sh), 0.0f);
        }
        *(float4*)(sA + k*NT + c) = v;
    }
    __syncthreads();

    u64 acc[TM][TN/2];
    #pragma unroll
    for (int j = 0; j < TM; j++)
        #pragma unroll
        for (int q = 0; q < TN/2; q++) acc[j][q] = 0ull;

    #pragma unroll 2
    for (int k = 0; k < K; k++) {
        u64 av[TN/2];
        #pragma unroll
        for (int q = 0; q < TN/4; q++) {            // FIXED: TN/4 ulonglong2 loads = TN floats
            ulonglong2 tmp = *(const ulonglong2*)(sA + k*NT + tn*TN + q*4);
            av[q*2] = tmp.x; av[q*2 + 1] = tmp.y;
        }
        #pragma unroll
        for (int j = 0; j < TM; j += 4) {
            float4 wv = *(const float4*)(sW + k*M + tm*TM + j);
            u64 w0 = pk2(wv.x, wv.x);
            u64 w1 = pk2(wv.y, wv.y);
            u64 w2 = pk2(wv.z, wv.z);
            u64 w3 = pk2(wv.w, wv.w);
            #pragma unroll
            for (int q = 0; q < TN/2; q++) ffma2(acc[j+0][q], av[q], w0);
            #pragma unroll
            for (int q = 0; q < TN/2; q++) ffma2(acc[j+1][q], av[q], w1);
            #pragma unroll
            for (int q = 0; q < TN/2; q++) ffma2(acc[j+2][q], av[q], w2);
            #pragma unroll
            for (int q = 0; q < TN/2; q++) ffma2(acc[j+3][q], av[q], w3);
        }
    }

    // epilogue: bias, store, partial stats
    float ps[TM], pq[TM];
    #pragma unroll
    for (int j = 0; j < TM; j++) {
        int m = tm*TM + j;
        float bsv = bias[m];
        float vals[TN];
        #pragma unroll
        for (int q = 0; q < TN/2; q++) {
            float x, y; upk2(acc[j][q], x, y);
            vals[2*q] = x + bsv; vals[2*q + 1] = y + bsv;
        }
        #pragma unroll
        for (int q = 0; q < TN/4; q++)
            *(float4*)(out + (size_t)m*PTOT + n0 + tn*TN + q*4) =
                make_float4(vals[4*q], vals[4*q+1], vals[4*q+2], vals[4*q+3]);
        float s = 0.0f, q2 = 0.0f;
        #pragma unroll
        for (int p = 0; p < TN; p++) { s += vals[p]; q2 = fmaf(vals[p], vals[p], q2); }
        ps[j] = s; pq[j] = q2;
    }
    __syncthreads();
    float* red = sA;                 // M*16 sums, M*16 sq
    #pragma unroll
    for (int j = 0; j < TM; j++) {
        int m = tm*TM + j;
        red[m*16 + tn] = ps[j];
        red[M*16 + m*16 + tn] = pq[j];
    }
    __syncthreads();
    if (t < M) {
        float s = 0.0f, q2 = 0.0f;
        #pragma unroll
        for (int i = 0; i < 16; i++) { s += red[t*16 + i]; q2 += red[M*16 + t*16 + i]; }
        psum[(size_t)t*nblk + blockIdx.x] = s;
        psq [(size_t)t*nblk + blockIdx.x] = q2;
    }
}

// =======================================================================
// 4) Reduce partials -> BN scale/shift
// =======================================================================
__global__ __launch_bounds__(256) void reduce_stats_kernel(const float* __restrict__ psum,
                                                           const float* __restrict__ psq,
                                                           const float* __restrict__ g,
                                                           const float* __restrict__ bt,
                                                           int nblk) {
    int c = blockIdx.x, t = threadIdx.x;
    float s = 0.0f, q = 0.0f;
    for (int i = t; i < nblk; i += 256) {
        s += psum[(size_t)c*nblk + i];
        q += psq [(size_t)c*nblk + i];
    }
    __shared__ float ss[256], sq[256];
    ss[t] = s; sq[t] = q;
    __syncthreads();
    for (int o = 128; o; o >>= 1) {
        if (t < o) { ss[t] += ss[t + o]; sq[t] += sq[t + o]; }
        __syncthreads();
    }
    if (t == 0) {
        float mu  = ss[0] / (float)PTOT;
        float var = sq[0] / (float)PTOT - mu * mu;
        float sc  = rsqrtf(var + 1e-5f) * g[c];
        g_scale[c] = sc;
        g_shift[c] = bt[c] - mu * sc;
    }
}

// =======================================================================
// 5) Fused BN+ReLU+max-pool over K, write transposed [B][128][S]
// =======================================================================
__global__ __launch_bounds__(256) void maxpool_kernel(const float* __restrict__ x,
                                                      float* __restrict__ out) {
    int c = blockIdx.x >> 4, b = blockIdx.x & 15;
    float sc = g_scale[c], sh = g_shift[c];
    for (int s = threadIdx.x; s < SS; s += 256) {
        const float4* p = (const float4*)(x + (size_t)c*PTOT + (size_t)(b*SS + s)*KK);
        float mx = -3.4e38f, mn = 3.4e38f;
        #pragma unroll
        for (int q = 0; q < 8; q++) {
            float4 v = p[q];
            mx = fmaxf(mx, fmaxf(fmaxf(v.x, v.y), fmaxf(v.z, v.w)));
            mn = fminf(mn, fminf(fminf(v.x, v.y), fminf(v.z, v.w)));
        }
        float r = fmaf((sc >= 0.0f ? mx : mn), sc, sh);
        out[(size_t)BB*3*SS + ((size_t)(b*C3 + c))*SS + s] = fmaxf(r, 0.0f);
    }
}

// 6) new_xyz transpose to [B, 3, S] at output head
__global__ __launch_bounds__(256) void outxyz_kernel(float* __restrict__ out) {
    int i = blockIdx.x * 256 + threadIdx.x;
    if (i >= BB*3*SS) return;
    int s = i & 1023;
    int bd = i >> 10;
    int b = bd / 3, d = bd - b * 3;
    out[i] = g_newxyz[((size_t)b * SS + s) * 3 + d];
}

// =======================================================================
extern "C" void kernel_launch(void* const* d_in, const int* in_sizes, int n_in,
                              void* d_out, int out_size) {
    const float* xyz = (const float*)d_in[0];
    const float* pts = (const float*)d_in[1];
    const float* w0  = (const float*)d_in[2];
    const float* b0  = (const float*)d_in[3];
    const float* g0  = (const float*)d_in[4];
    const float* bt0 = (const float*)d_in[5];
    const float* w1  = (const float*)d_in[6];
    const float* b1  = (const float*)d_in[7];
    const float* g1  = (const float*)d_in[8];
    const float* bt1 = (const float*)d_in[9];
    const float* w2  = (const float*)d_in[10];
    const float* b2  = (const float*)d_in[11];
    const float* g2  = (const float*)d_in[12];
    const float* bt2 = (const float*)d_in[13];
    float* out = (float*)d_out;

    float *pA, *pB, *pT, *pw0, *pw1, *pw2, *pps, *ppq;
    cudaGetSymbolAddress((void**)&pA, g_bufA);
    cudaGetSymbolAddress((void**)&pB, g_bufB);
    cudaGetSymbolAddress((void**)&pT, g_ptsT);
    cudaGetSymbolAddress((void**)&pw0, g_wt0);
    cudaGetSymbolAddress((void**)&pw1, g_wt1);
    cudaGetSymbolAddress((void**)&pw2, g_wt2);
    cudaGetSymbolAddress((void**)&pps, g_psum);
    cudaGetSymbolAddress((void**)&ppq, g_psq);

    const int smemM = (3*NN + 1056 + 16) * 4;            // 53536 B (xyz + sIdx/red)
    const int smem1 = (C0*C1 + C0*256) * 4;              // 85760
    const int smem2 = (C1*C1 + C1*256) * 4;              // 81920
    const int smem3 = (C1*C3 + C1*128) * 4;              // 65536
    cudaFuncSetAttribute(mega_kernel, cudaFuncAttributeMaxDynamicSharedMemorySize, smemM);
    cudaFuncSetAttribute(gemm_kernel<64, 67, 16, false>, cudaFuncAttributeMaxDynamicSharedMemorySize, smem1);
    cudaFuncSetAttribute(gemm_kernel<64, 64, 16, true>,  cudaFuncAttributeMaxDynamicSharedMemorySize, smem2);
    cudaFuncSetAttribute(gemm_kernel<128, 64, 8, true>,  cudaFuncAttributeMaxDynamicSharedMemorySize, smem3);

    reset_kernel<<<1, 32>>>();
    mega_kernel<<<BB + 128, 1024, smemM>>>(xyz, pts, pT, pA);
    wtrans_all_kernel<<<(C0*C1 + C1*C1 + C1*C3 + 255)/256, 256>>>(w0, w1, w2);

    // Layer 1: 67 -> 64 (A -> B), N-tile 256
    gemm_kernel<64, 67, 16, false><<<PTOT/256, 256, smem1>>>(pA, pB, pw0, b0, pps, ppq, PTOT/256);
    reduce_stats_kernel<<<C1, 256>>>(pps, ppq, g0, bt0, PTOT/256);

    // Layer 2: 64 -> 64 (B -> A), BN+ReLU fused on load, N-tile 256
    gemm_kernel<64, 64, 16, true><<<PTOT/256, 256, smem2>>>(pB, pA, pw1, b1, pps, ppq, PTOT/256);
    reduce_stats_kernel<<<C1, 256>>>(pps, ppq, g1, bt1, PTOT/256);

    // Layer 3: 64 -> 128 (A -> B), BN+ReLU fused on load, N-tile 128
    gemm_kernel<128, 64, 8, true><<<PTOT/128, 256, smem3>>>(pA, pB, pw2, b2, pps, ppq, PTOT/128);
    reduce_stats_kernel<<<C3, 256>>>(pps, ppq, g2, bt2, PTOT/128);

    maxpool_kernel<<<C3*BB, 256>>>(pB, out);
    outxyz_kernel<<<(BB*3*SS + 255)/256, 256>>>(out);
}

// round 9
// speedup vs baseline: 11.7129x; 1.3855x over previous
#include <cuda_runtime.h>

// Problem constants
#define BB 16
#define NN 4096
#define SS 1024
#define KK 32
#define PTOT (BB*SS*KK)      // 524288 positions
#define C0 67
#define C1 64
#define C3 128

typedef unsigned long long u64;

// ---------------- device scratch (no allocation allowed) ----------------
__device__ float g_newxyz[BB*SS*3];
__device__ float g_ptsT[(size_t)BB*NN*64];   // 16MB  [b][n][c]
__device__ float g_bufA[(size_t)PTOT*128];   // 256MB
__device__ float g_bufB[(size_t)PTOT*128];   // 256MB (L3: reused as max/min buffers)
__device__ float g_psum[128*4096];
__device__ float g_psq[128*4096];
__device__ float g_scale[128];
__device__ float g_shift[128];
__device__ float g_wt0[C0*C1];
__device__ float g_wt1[C1*C1];
__device__ float g_wt2[C1*C3];
__device__ int   g_flag[BB];                 // fps done per batch
__device__ int   g_tdone;                    // transpose barrier

// ---------------- f32x2 helpers ----------------
__device__ __forceinline__ u64 pk2(float x, float y) {
    u64 r; asm("mov.b64 %0, {%1,%2};" : "=l"(r) : "f"(x), "f"(y)); return r;
}
__device__ __forceinline__ void upk2(u64 v, float& x, float& y) {
    asm("mov.b64 {%0,%1}, %2;" : "=f"(x), "=f"(y) : "l"(v));
}
__device__ __forceinline__ void ffma2(u64& d, u64 a, u64 b) {
    asm("fma.rn.f32x2 %0, %1, %2, %0;" : "+l"(d) : "l"(a), "l"(b));
}
// bank-conflict swizzle: XOR 16B-chunk index with 128B-row index (within 1KB window)
__device__ __forceinline__ unsigned swz(unsigned byteoff) {
    return byteoff ^ ((byteoff >> 3) & 0x70u);
}

__device__ __forceinline__ float sqdist_exact(float dx, float dy, float dz) {
    return __fadd_rn(__fadd_rn(__fmul_rn(dx, dx), __fmul_rn(dy, dy)), __fmul_rn(dz, dz));
}

// =======================================================================
// 0) reset flags (must run every replay)
// =======================================================================
__global__ void reset_kernel() {
    int t = threadIdx.x;
    if (t < BB) g_flag[t] = 0;
    if (t == BB) g_tdone = 0;
}

// =======================================================================
// 1) MEGA front-end kernel: 144 blocks x 1024 threads, all resident.
// =======================================================================
extern __shared__ float smd[];

__global__ __launch_bounds__(1024) void mega_kernel(const float* __restrict__ xyz,
                                                    const float* __restrict__ pts,
                                                    float* __restrict__ ptsT,
                                                    float* __restrict__ feat) {
    const int t = threadIdx.x;
    const int w = t >> 5, lane = t & 31;

    if (blockIdx.x < BB) {
        // ---------------- FPS ----------------
        int b = blockIdx.x;
        for (int i = t; i < 3*NN; i += 1024)
            smd[i] = xyz[(size_t)b*3*NN + i];
        __syncthreads();

        float4 X = ((const float4*)smd)[t];
        float4 Y = ((const float4*)(smd + NN))[t];
        float4 Z = ((const float4*)(smd + 2*NN))[t];
        float d0 = 1e10f, d1 = 1e10f, d2 = 1e10f, d3 = 1e10f;

        unsigned* sv = (unsigned*)(smd + 3*NN);
        int*      si = (int*)(smd + 3*NN + 32);
        int*      sfar = (int*)(smd + 3*NN + 64);

        int far = 0;
        for (int s = 0; s < SS; s++) {
            float cx = smd[far], cy = smd[NN + far], cz = smd[2*NN + far];
            if (t == 0) {
                g_newxyz[(b*SS + s)*3 + 0] = cx;
                g_newxyz[(b*SS + s)*3 + 1] = cy;
                g_newxyz[(b*SS + s)*3 + 2] = cz;
            }
            d0 = fminf(d0, sqdist_exact(X.x - cx, Y.x - cy, Z.x - cz));
            d1 = fminf(d1, sqdist_exact(X.y - cx, Y.y - cy, Z.y - cz));
            d2 = fminf(d2, sqdist_exact(X.z - cx, Y.z - cy, Z.z - cz));
            d3 = fminf(d3, sqdist_exact(X.w - cx, Y.w - cy, Z.w - cz));

            float bv = d0; int bi = 4*t;
            if (d1 > bv) { bv = d1; bi = 4*t + 1; }
            if (d2 > bv) { bv = d2; bi = 4*t + 2; }
            if (d3 > bv) { bv = d3; bi = 4*t + 3; }

            unsigned key = __float_as_uint(bv);
            unsigned wm = __reduce_max_sync(0xffffffffu, key);
            unsigned mm = __ballot_sync(0xffffffffu, key == wm);
            int ln = __ffs(mm) - 1;
            int wbi = __shfl_sync(0xffffffffu, bi, ln);
            if (lane == 0) { sv[w] = wm; si[w] = wbi; }
            __syncthreads();
            if (t < 32) {
                unsigned k2 = sv[t]; int i2 = si[t];
                unsigned wm2 = __reduce_max_sync(0xffffffffu, k2);
                unsigned m2 = __ballot_sync(0xffffffffu, k2 == wm2);
                int l2 = __ffs(m2) - 1;
                int f2 = __shfl_sync(0xffffffffu, i2, l2);
                if (t == 0) *sfar = f2;
            }
            __syncthreads();
            far = *sfar;
        }
        __threadfence();
        if (t == 0) atomicExch(&g_flag[b], 1);
        return;
    }

    // ---------------- workers ----------------
    int wb = blockIdx.x - BB;          // 0..127
    int b = wb >> 3, sub = wb & 7;

    // Phase A: pts transpose share (32 tiles of 32x32)
    {
        float* tile = smd;
        for (int tix = wb*32; tix < wb*32 + 32; tix++) {
            int tb = tix >> 8, rem = tix & 255;
            int ct = rem >> 7, nt = rem & 127;
            tile[lane*33 + w] = pts[((size_t)tb*64 + ct*32 + w)*NN + nt*32 + lane];
            __syncthreads();
            ptsT[((size_t)tb*NN + nt*32 + w)*64 + ct*32 + lane] = tile[w*33 + lane];
            __syncthreads();
        }
        __threadfence();
        if (t == 0) atomicAdd(&g_tdone, 1);
    }
    if (t == 0) { while (atomicAdd(&g_tdone, 0) < 128) __nanosleep(128); }
    if (t == 0) { while (atomicAdd(&g_flag[b], 0) == 0) __nanosleep(256); }
    __syncthreads();
    __threadfence();

    for (int i = t; i < 3*NN; i += 1024)
        smd[i] = xyz[(size_t)b*3*NN + i];
    __syncthreads();

    int* sIdx = (int*)(smd + 3*NN);

    for (int r = 0; r < 4; r++) {
        int bs = b*1024 + sub*128 + w*4 + r;
        float cx = g_newxyz[bs*3], cy = g_newxyz[bs*3 + 1], cz = g_newxyz[bs*3 + 2];
        float snew = cx*cx + cy*cy + cz*cz;
        int cnt = 0, first = -1;
        for (int n0 = 0; n0 < NN && cnt < KK; n0 += 32) {
            int n = n0 + lane;
            float px = smd[n], py = smd[NN + n], pz = smd[2*NN + n];
            float sp = px*px + py*py + pz*pz;
            float d = snew + sp - 2.0f*(cx*px + cy*py + cz*pz);
            bool in = (d <= 0.04f);
            unsigned m = __ballot_sync(0xffffffffu, in);
            if (first < 0 && m) first = n0 + __ffs(m) - 1;
            int rank = __popc(m & ((1u << lane) - 1u));
            if (in && cnt + rank < KK) sIdx[w*32 + cnt + rank] = n;
            cnt += __popc(m);
        }
        if (lane >= cnt) sIdx[w*32 + lane] = first;
        __syncwarp();

        int n = sIdx[w*32 + lane];
        #pragma unroll
        for (int c = 0; c < 3; c++)
            feat[(size_t)c*PTOT + bs*KK + lane] = smd[c*NN + n] - g_newxyz[bs*3 + c];
        const float4* row = (const float4*)(ptsT + ((size_t)b*NN + n)*64);
        #pragma unroll
        for (int c4 = 0; c4 < 16; c4++) {
            float4 v = row[c4];
            feat[(size_t)(3 + 4*c4 + 0)*PTOT + bs*KK + lane] = v.x;
            feat[(size_t)(3 + 4*c4 + 1)*PTOT + bs*KK + lane] = v.y;
            feat[(size_t)(3 + 4*c4 + 2)*PTOT + bs*KK + lane] = v.z;
            feat[(size_t)(3 + 4*c4 + 3)*PTOT + bs*KK + lane] = v.w;
        }
        __syncwarp();
    }
}

// =======================================================================
// 2) All three weight transposes in one launch: wt[k][m] = W[m][k]
// =======================================================================
__global__ void wtrans_all_kernel(const float* __restrict__ w0,
                                  const float* __restrict__ w1,
                                  const float* __restrict__ w2) {
    int i = blockIdx.x * 256 + threadIdx.x;
    if (i < C0*C1) {
        int k = i / C1, m = i - k*C1;
        g_wt0[i] = w0[m*C0 + k];
    } else if (i < C0*C1 + C1*C1) {
        int j = i - C0*C1, k = j / C1, m = j - k*C1;
        g_wt1[j] = w1[m*C1 + k];
    } else if (i < C0*C1 + C1*C1 + C1*C3) {
        int j = i - C0*C1 - C1*C1, k = j / C3, m = j - k*C3;
        g_wt2[j] = w2[m*C1 + k];
    }
}

// =======================================================================
// 3) GEMM: out[M][PTOT] = Wt^T x in[K][PTOT] (+bias). Optional BN+ReLU
//    fused on input load; per-block BN-stat partials in epilogue.
//    sA is XOR-swizzled to kill LDS bank conflicts.
//    POOL: don't store activations; emit per-(m, centroid) max/min instead
//    (NT must be 128 so a block covers exactly 4 centroids of K=32).
// =======================================================================
extern __shared__ float smg[];

template<int M, int K, int TN, bool BN, bool POOL>
__global__ __launch_bounds__(256) void gemm_kernel(const float* __restrict__ in,
                                                   float* __restrict__ out,
                                                   const float* __restrict__ wt,
                                                   const float* __restrict__ bias,
                                                   float* __restrict__ psum,
                                                   float* __restrict__ psq,
                                                   int nblk) {
    constexpr int TM = M / 16;
    constexpr int NT = 16 * TN;
    float* sW = smg;            // K*M
    char*  sAb = (char*)(smg + K*M);   // K*NT floats, swizzled
    const int t = threadIdx.x;
    const int tn = t & 15, tm = t >> 4;
    const int n0 = blockIdx.x * NT;

    for (int i = t; i < K*M; i += 256) sW[i] = wt[i];
    for (int i = t; i < K*(NT/4); i += 256) {
        int k = i / (NT/4), c = (i % (NT/4)) << 2;
        float4 v = *(const float4*)(in + (size_t)k*PTOT + n0 + c);
        if (BN) {
            float sc = g_scale[k], sh = g_shift[k];
            v.x = fmaxf(fmaf(v.x, sc, sh), 0.0f);
            v.y = fmaxf(fmaf(v.y, sc, sh), 0.0f);
            v.z = fmaxf(fmaf(v.z, sc, sh), 0.0f);
            v.w = fmaxf(fmaf(v.w, sc, sh), 0.0f);
        }
        *(float4*)(sAb + swz((unsigned)(k*NT + c)*4u)) = v;
    }
    __syncthreads();

    u64 acc[TM][TN/2];
    #pragma unroll
    for (int j = 0; j < TM; j++)
        #pragma unroll
        for (int q = 0; q < TN/2; q++) acc[j][q] = 0ull;

    #pragma unroll 2
    for (int k = 0; k < K; k++) {
        u64 av[TN/2];
        #pragma unroll
        for (int q = 0; q < TN/4; q++) {
            ulonglong2 tmp = *(const ulonglong2*)(sAb + swz((unsigned)(k*NT + tn*TN + q*4)*4u));
            av[q*2] = tmp.x; av[q*2 + 1] = tmp.y;
        }
        #pragma unroll
        for (int j = 0; j < TM; j += 4) {
            float4 wv = *(const float4*)(sW + k*M + tm*TM + j);
            u64 w0 = pk2(wv.x, wv.x);
            u64 w1 = pk2(wv.y, wv.y);
            u64 w2 = pk2(wv.z, wv.z);
            u64 w3 = pk2(wv.w, wv.w);
            #pragma unroll
            for (int q = 0; q < TN/2; q++) ffma2(acc[j+0][q], av[q], w0);
            #pragma unroll
            for (int q = 0; q < TN/2; q++) ffma2(acc[j+1][q], av[q], w1);
            #pragma unroll
            for (int q = 0; q < TN/2; q++) ffma2(acc[j+2][q], av[q], w2);
            #pragma unroll
            for (int q = 0; q < TN/2; q++) ffma2(acc[j+3][q], av[q], w3);
        }
    }

    // epilogue: bias, (store | pool), partial stats
    float ps[TM], pq[TM], pmx[TM], pmn[TM];
    #pragma unroll
    for (int j = 0; j < TM; j++) {
        int m = tm*TM + j;
        float bsv = bias[m];
        float vals[TN];
        #pragma unroll
        for (int q = 0; q < TN/2; q++) {
            float x, y; upk2(acc[j][q], x, y);
            vals[2*q] = x + bsv; vals[2*q + 1] = y + bsv;
        }
        if (!POOL) {
            #pragma unroll
            for (int q = 0; q < TN/4; q++)
                *(float4*)(out + (size_t)m*PTOT + n0 + tn*TN + q*4) =
                    make_float4(vals[4*q], vals[4*q+1], vals[4*q+2], vals[4*q+3]);
        }
        float s = 0.0f, q2 = 0.0f, mx = -3.4e38f, mn = 3.4e38f;
        #pragma unroll
        for (int p = 0; p < TN; p++) {
            s += vals[p]; q2 = fmaf(vals[p], vals[p], q2);
            if (POOL) { mx = fmaxf(mx, vals[p]); mn = fminf(mn, vals[p]); }
        }
        ps[j] = s; pq[j] = q2; pmx[j] = mx; pmn[j] = mn;
    }
    __syncthreads();
    float* red = (float*)sAb;        // M*16 sums, M*16 sq [, M*16 max, M*16 min]
    #pragma unroll
    for (int j = 0; j < TM; j++) {
        int m = tm*TM + j;
        red[m*16 + tn] = ps[j];
        red[M*16 + m*16 + tn] = pq[j];
        if (POOL) {
            red[2*M*16 + m*16 + tn] = pmx[j];
            red[3*M*16 + m*16 + tn] = pmn[j];
        }
    }
    __syncthreads();
    if (t < M) {
        float s = 0.0f, q2 = 0.0f;
        #pragma unroll
        for (int i = 0; i < 16; i++) { s += red[t*16 + i]; q2 += red[M*16 + t*16 + i]; }
        psum[(size_t)t*nblk + blockIdx.x] = s;
        psq [(size_t)t*nblk + blockIdx.x] = q2;
    }
    if (POOL) {
        // 4 centroids per block (NT=128, K=32); tn group g = tn/4
        for (int p = t; p < 4*M; p += 256) {
            int m = p >> 2, g = p & 3;
            float mx = red[2*M*16 + m*16 + g*4];
            float mn = red[3*M*16 + m*16 + g*4];
            #pragma unroll
            for (int i = 1; i < 4; i++) {
                mx = fmaxf(mx, red[2*M*16 + m*16 + g*4 + i]);
                mn = fminf(mn, red[3*M*16 + m*16 + g*4 + i]);
            }
            int bsg = blockIdx.x*4 + g;
            out[(size_t)m*(BB*SS) + bsg] = mx;
            out[(size_t)C3*(BB*SS) + (size_t)m*(BB*SS) + bsg] = mn;
        }
    }
}

// =======================================================================
// 4) Reduce partials -> BN scale/shift
// =======================================================================
__global__ __launch_bounds__(256) void reduce_stats_kernel(const float* __restrict__ psum,
                                                           const float* __restrict__ psq,
                                                           const float* __restrict__ g,
                                                           const float* __restrict__ bt,
                                                           int nblk) {
    int c = blockIdx.x, t = threadIdx.x;
    float s = 0.0f, q = 0.0f;
    for (int i = t; i < nblk; i += 256) {
        s += psum[(size_t)c*nblk + i];
        q += psq [(size_t)c*nblk + i];
    }
    __shared__ float ss[256], sq[256];
    ss[t] = s; sq[t] = q;
    __syncthreads();
    for (int o = 128; o; o >>= 1) {
        if (t < o) { ss[t] += ss[t + o]; sq[t] += sq[t + o]; }
        __syncthreads();
    }
    if (t == 0) {
        float mu  = ss[0] / (float)PTOT;
        float var = sq[0] / (float)PTOT - mu * mu;
        float sc  = rsqrtf(var + 1e-5f) * g[c];
        g_scale[c] = sc;
        g_shift[c] = bt[c] - mu * sc;
    }
}

// =======================================================================
// 5) Final: BN applied to pooled max/min, write [B][128][S]
// =======================================================================
__global__ __launch_bounds__(256) void maxpool2_kernel(const float* __restrict__ mxb,
                                                       const float* __restrict__ mnb,
                                                       float* __restrict__ out) {
    int i = blockIdx.x * 256 + threadIdx.x;       // 128*16384
    int m = i >> 14, bs = i & 16383;
    float sc = g_scale[m], sh = g_shift[m];
    float v = (sc >= 0.0f) ? mxb[i] : mnb[i];
    float r = fmaf(v, sc, sh);
    int b = bs >> 10, s = bs & 1023;
    out[(size_t)BB*3*SS + ((size_t)(b*C3 + m))*SS + s] = fmaxf(r, 0.0f);
}

// 6) new_xyz transpose to [B, 3, S] at output head
__global__ __launch_bounds__(256) void outxyz_kernel(float* __restrict__ out) {
    int i = blockIdx.x * 256 + threadIdx.x;
    if (i >= BB*3*SS) return;
    int s = i & 1023;
    int bd = i >> 10;
    int b = bd / 3, d = bd - b * 3;
    out[i] = g_newxyz[((size_t)b * SS + s) * 3 + d];
}

// =======================================================================
extern "C" void kernel_launch(void* const* d_in, const int* in_sizes, int n_in,
                              void* d_out, int out_size) {
    const float* xyz = (const float*)d_in[0];
    const float* pts = (const float*)d_in[1];
    const float* w0  = (const float*)d_in[2];
    const float* b0  = (const float*)d_in[3];
    const float* g0  = (const float*)d_in[4];
    const float* bt0 = (const float*)d_in[5];
    const float* w1  = (const float*)d_in[6];
    const float* b1  = (const float*)d_in[7];
    const float* g1  = (const float*)d_in[8];
    const float* bt1 = (const float*)d_in[9];
    const float* w2  = (const float*)d_in[10];
    const float* b2  = (const float*)d_in[11];
    const float* g2  = (const float*)d_in[12];
    const float* bt2 = (const float*)d_in[13];
    float* out = (float*)d_out;

    float *pA, *pB, *pT, *pw0, *pw1, *pw2, *pps, *ppq;
    cudaGetSymbolAddress((void**)&pA, g_bufA);
    cudaGetSymbolAddress((void**)&pB, g_bufB);
    cudaGetSymbolAddress((void**)&pT, g_ptsT);
    cudaGetSymbolAddress((void**)&pw0, g_wt0);
    cudaGetSymbolAddress((void**)&pw1, g_wt1);
    cudaGetSymbolAddress((void**)&pw2, g_wt2);
    cudaGetSymbolAddress((void**)&pps, g_psum);
    cudaGetSymbolAddress((void**)&ppq, g_psq);

    const int smemM = (3*NN + 1056 + 16) * 4;            // 53536 B
    const int smem1 = (C0*C1 + C0*256) * 4;              // 85760
    const int smem2 = (C1*C1 + C1*256) * 4;              // 81920
    const int smem3 = (C1*C3 + C1*128) * 4;              // 65536
    cudaFuncSetAttribute(mega_kernel, cudaFuncAttributeMaxDynamicSharedMemorySize, smemM);
    cudaFuncSetAttribute(gemm_kernel<64, 67, 16, false, false>, cudaFuncAttributeMaxDynamicSharedMemorySize, smem1);
    cudaFuncSetAttribute(gemm_kernel<64, 64, 16, true, false>,  cudaFuncAttributeMaxDynamicSharedMemorySize, smem2);
    cudaFuncSetAttribute(gemm_kernel<128, 64, 8, true, true>,   cudaFuncAttributeMaxDynamicSharedMemorySize, smem3);

    reset_kernel<<<1, 32>>>();
    mega_kernel<<<BB + 128, 1024, smemM>>>(xyz, pts, pT, pA);
    wtrans_all_kernel<<<(C0*C1 + C1*C1 + C1*C3 + 255)/256, 256>>>(w0, w1, w2);

    // Layer 1: 67 -> 64 (A -> B), N-tile 256
    gemm_kernel<64, 67, 16, false, false><<<PTOT/256, 256, smem1>>>(pA, pB, pw0, b0, pps, ppq, PTOT/256);
    reduce_stats_kernel<<<C1, 256>>>(pps, ppq, g0, bt0, PTOT/256);

    // Layer 2: 64 -> 64 (B -> A), BN+ReLU fused on load, N-tile 256
    gemm_kernel<64, 64, 16, true, false><<<PTOT/256, 256, smem2>>>(pB, pA, pw1, b1, pps, ppq, PTOT/256);
    reduce_stats_kernel<<<C1, 256>>>(pps, ppq, g1, bt1, PTOT/256);

    // Layer 3: 64 -> 128 (A -> pooled max/min in B), N-tile 128
    gemm_kernel<128, 64, 8, true, true><<<PTOT/128, 256, smem3>>>(pA, pB, pw2, b2, pps, ppq, PTOT/128);
    reduce_stats_kernel<<<C3, 256>>>(pps, ppq, g2, bt2, PTOT/128);

    maxpool2_kernel<<<(C3*BB*SS)/256, 256>>>(pB, pB + (size_t)C3*BB*SS, out);
    outxyz_kernel<<<(BB*3*SS + 255)/256, 256>>>(out);
}